// round 4
// baseline (speedup 1.0000x reference)
#include <cuda_runtime.h>
#include <cstdint>
#include <math.h>

#define BB 64
#define SS 512
#define EE 256
#define HH 512
#define GG 2048
#define BSH (BB*SS*HH)
#define NBLK 128

// scan smem layout (float offsets)
#define SW_OFF   0        // [16][512] W_all rows (q*4+g)
#define SWD_OFF  8192     // [4][512]  W_d rows (q)
#define X_OFF    10240    // 4 x (h[64][68] + c[64][68]) = (half,slot) blocks of 8704
#define XSLOT    8704
#define XC       4352
#define RED_OFF  45056    // [2 half][2 q2][64 b][10]
#define SMEM_FLOATS 47616
#define SCAN_SMEM (SMEM_FLOATS*4)

__device__ float g_uproj[BB*SS*GG];
__device__ float g_h[2][BB*HH];
__device__ float g_c[2][BB*HH];
__device__ unsigned int g_ctr;

// ---------------- helpers ----------------
__device__ __forceinline__ uint32_t smem_u32(const void* p) {
    uint32_t a;
    asm("{ .reg .u64 t; cvta.to.shared.u64 t, %1; cvt.u32.u64 %0, t; }" : "=r"(a) : "l"(p));
    return a;
}
__device__ __forceinline__ void ffma2(unsigned long long& d, unsigned long long a, unsigned long long b) {
    asm("fma.rn.f32x2 %0, %1, %2, %0;" : "+l"(d) : "l"(a), "l"(b));
}
__device__ __forceinline__ unsigned long long dup2(float a) {
    unsigned long long r;
    asm("mov.b64 %0, {%1,%1};" : "=l"(r) : "f"(a));
    return r;
}
__device__ __forceinline__ float fold2(unsigned long long v) {
    float lo, hi;
    asm("mov.b64 {%0,%1}, %2;" : "=f"(lo), "=f"(hi) : "l"(v));
    return lo + hi;
}
__device__ __forceinline__ void cp16(uint32_t dst, const void* src) {
    asm volatile("cp.async.ca.shared.global [%0], [%1], 16;" :: "r"(dst), "l"(src));
}
#define CP_COMMIT() asm volatile("cp.async.commit_group;" ::: "memory")
#define CP_WAIT1()  asm volatile("cp.async.wait_group 1;" ::: "memory")
#define CP_WAIT0()  asm volatile("cp.async.wait_group 0;" ::: "memory")
__device__ __forceinline__ void barn(int id) {
    asm volatile("bar.sync %0, %1;" :: "r"(id), "r"(128) : "memory");
}
__device__ __forceinline__ float sigf(float x) { return 1.0f / (1.0f + expf(-x)); }

// ---------------- init ----------------
__global__ void init_state() {
    int i = blockIdx.x * 256 + threadIdx.x;  // 32768
    g_h[0][i] = 0.f;
    g_c[0][i] = 0.f;
    if (i == 0) g_ctr = 0u;
}

// ---------------- u_proj GEMM with FFMA2 ----------------
__global__ void __launch_bounds__(256) gemm_uproj(
    const float* __restrict__ A, const float* __restrict__ W, const float* __restrict__ bias)
{
    __shared__ float As[8][132];
    __shared__ float Bs[8][132];
    const int tid = threadIdx.x;
    const int bm = blockIdx.y * 128, bn = blockIdx.x * 128;
    const int tx = tid & 15, ty = tid >> 4;
    const int lrow = tid >> 1, lk = (tid & 1) * 4;
    const float* Aptr = A + (size_t)(bm + lrow) * EE + lk;
    const float* Wptr = W + (size_t)(bn + lrow) * EE + lk;

    unsigned long long acc2[8][4];
#pragma unroll
    for (int r = 0; r < 8; r++)
#pragma unroll
        for (int c = 0; c < 4; c++) acc2[r][c] = 0ull;

    float4 av = *(const float4*)(Aptr);
    float4 bv = *(const float4*)(Wptr);

    for (int k0 = 0; k0 < EE; k0 += 8) {
        __syncthreads();
        As[lk+0][lrow]=av.x; As[lk+1][lrow]=av.y; As[lk+2][lrow]=av.z; As[lk+3][lrow]=av.w;
        Bs[lk+0][lrow]=bv.x; Bs[lk+1][lrow]=bv.y; Bs[lk+2][lrow]=bv.z; Bs[lk+3][lrow]=bv.w;
        __syncthreads();
        if (k0 + 8 < EE) { av = *(const float4*)(Aptr+k0+8); bv = *(const float4*)(Wptr+k0+8); }
#pragma unroll
        for (int kk = 0; kk < 8; kk++) {
            float4 a0 = *(const float4*)&As[kk][ty*8];
            float4 a1 = *(const float4*)&As[kk][ty*8+4];
            ulonglong2 b0 = *(const ulonglong2*)&Bs[kk][tx*8];
            ulonglong2 b1 = *(const ulonglong2*)&Bs[kk][tx*8+4];
            float ar[8] = {a0.x,a0.y,a0.z,a0.w,a1.x,a1.y,a1.z,a1.w};
            unsigned long long br2[4] = {b0.x, b0.y, b1.x, b1.y};
#pragma unroll
            for (int r = 0; r < 8; r++) {
                unsigned long long ad = dup2(ar[r]);
#pragma unroll
                for (int c = 0; c < 4; c++) ffma2(acc2[r][c], ad, br2[c]);
            }
        }
    }

    float bsr[8];
#pragma unroll
    for (int c = 0; c < 8; c++) bsr[c] = bias[bn + tx*8 + c];
#pragma unroll
    for (int r = 0; r < 8; r++) {
        float accv[8];
#pragma unroll
        for (int c = 0; c < 4; c++) {
            float lo, hi;
            asm("mov.b64 {%0,%1}, %2;" : "=f"(lo), "=f"(hi) : "l"(acc2[r][c]));
            accv[2*c] = lo; accv[2*c+1] = hi;
        }
        float* cp = g_uproj + (size_t)(bm + ty*8 + r) * GG + bn + tx*8;
        float4 o0 = {accv[0]+bsr[0], accv[1]+bsr[1], accv[2]+bsr[2], accv[3]+bsr[3]};
        float4 o1 = {accv[4]+bsr[4], accv[5]+bsr[5], accv[6]+bsr[6], accv[7]+bsr[7]};
        *(float4*)(cp) = o0; *(float4*)(cp + 4) = o1;
    }
}

// ---------------- persistent scan (FFMA2 + cp.async) ----------------
__global__ void __launch_bounds__(256, 1) lstm_scan(
    const float* __restrict__ ts,
    const float* __restrict__ Wall,
    const float* __restrict__ ball,
    const float* __restrict__ Wd,
    const float* __restrict__ bd,
    float* __restrict__ out)
{
    extern __shared__ float sm[];
    const int tid = threadIdx.x;
    const int bid = blockIdx.x;
    const int jbase = bid * 4;

    // ---- load weights into SMEM (once) ----
    for (int idx = tid; idx < 16*512; idx += 256) {
        int r = idx >> 9, k = idx & 511;
        int q = r >> 2, g = r & 3;
        sm[SW_OFF + idx] = Wall[(size_t)(g*512 + jbase + q) * 512 + k];
    }
    for (int idx = tid; idx < 4*512; idx += 256) {
        int q = idx >> 9, k = idx & 511;
        sm[SWD_OFF + idx] = Wd[(size_t)(jbase + q) * 512 + k];
    }

    // ---- phase-B identity ----
    const int jj = tid >> 6;          // 0..3
    const int b2 = tid & 63;          // batch
    const int j  = jbase + jj;
    const float bfb = __ldg(ball + j);
    const float bib = __ldg(ball + 512 + j);
    const float bob = __ldg(ball + 1024 + j);
    const float bcb = __ldg(ball + 1536 + j);
    const float bdj = __ldg(bd + j);

    // ---- compute identity ----
    const int half = tid >> 7;            // warps 0-3 half0, 4-7 half1
    const int w3   = (tid >> 5) & 3;
    const int lane = tid & 31;
    const int b_lo = lane & 15;
    const int q2   = lane >> 4;           // j-pair group
    const int b    = b_lo + w3 * 16;      // batch for compute

    // ---- staging identity ----
    const int stid = tid & 127;
    const int sbb  = stid >> 1;           // row 0..63
    const int part = stid & 1;            // 0/1: cols 0-31 / 32-63

    const uint32_t xbyte = smem_u32(sm + X_OFF);
    __syncthreads();

    for (int s = 0; s < SS; s++) {
        const float* hsrc = g_h[s & 1];
        const float* csrc = g_c[s & 1];

        // prefetch phase-B operands
        const float* up = g_uproj + ((size_t)b2 * SS + s) * GG;
        float u0 = __ldg(up + j);
        float u1 = __ldg(up + 512 + j);
        float u2 = __ldg(up + 1024 + j);
        float u3 = __ldg(up + 1536 + j);
        float tv = __ldg(ts + b2 * SS + s);
        float c_old = __ldcg(csrc + b2 * HH + j);

        // ---- issue tiles 0 and 1 ----
#pragma unroll
        for (int t0 = 0; t0 < 2; t0++) {
            int k0 = half * 256 + t0 * 64;
            uint32_t dh = xbyte + (uint32_t)(((half*2 + t0) * XSLOT + sbb*68 + part*32) * 4);
            const float* sh = hsrc + sbb * 512 + k0 + part * 32;
            const float* sc = csrc + sbb * 512 + k0 + part * 32;
#pragma unroll
            for (int i = 0; i < 8; i++) cp16(dh + i*16, sh + i*4);
#pragma unroll
            for (int i = 0; i < 8; i++) cp16(dh + XC*4 + i*16, sc + i*4);
            CP_COMMIT();
        }

        unsigned long long acc[2][5];
#pragma unroll
        for (int a = 0; a < 2; a++)
#pragma unroll
            for (int d = 0; d < 5; d++) acc[a][d] = 0ull;

        for (int t = 0; t < 4; t++) {
            if (t < 3) CP_WAIT1(); else CP_WAIT0();
            barn(1 + half);

            const int slot = t & 1;
            const int kg0 = half * 256 + t * 64;
            const float* hb = sm + X_OFF + (half*2 + slot) * XSLOT + b * 68;
            const float* cb = hb + XC;
#pragma unroll
            for (int k = 0; k < 64; k += 4) {
                ulonglong2 h2 = *(const ulonglong2*)(hb + k);
                ulonglong2 c2 = *(const ulonglong2*)(cb + k);
                const int kg = kg0 + k;
#pragma unroll
                for (int js = 0; js < 2; js++) {
                    const float* wr = sm + SW_OFF + ((q2*2 + js) * 4) * 512 + kg;
#pragma unroll
                    for (int g = 0; g < 4; g++) {
                        ulonglong2 wv = *(const ulonglong2*)(wr + g * 512);
                        ffma2(acc[js][g], wv.x, h2.x);
                        ffma2(acc[js][g], wv.y, h2.y);
                    }
                    ulonglong2 wd2 = *(const ulonglong2*)(sm + SWD_OFF + (q2*2 + js) * 512 + kg);
                    ffma2(acc[js][4], wd2.x, c2.x);
                    ffma2(acc[js][4], wd2.y, c2.y);
                }
            }

            barn(1 + half);
            if (t < 2) {   // issue tile t+2 into slot t&1
                int k0 = half * 256 + (t + 2) * 64;
                uint32_t dh = xbyte + (uint32_t)(((half*2 + slot) * XSLOT + sbb*68 + part*32) * 4);
                const float* sh = hsrc + sbb * 512 + k0 + part * 32;
                const float* sc = csrc + sbb * 512 + k0 + part * 32;
#pragma unroll
                for (int i = 0; i < 8; i++) cp16(dh + i*16, sh + i*4);
#pragma unroll
                for (int i = 0; i < 8; i++) cp16(dh + XC*4 + i*16, sc + i*4);
                CP_COMMIT();
            }
        }

        // ---- cross-half reduction ----
        {
            float* red = sm + RED_OFF + ((half*2 + q2) * 64 + b) * 10;
#pragma unroll
            for (int js = 0; js < 2; js++)
#pragma unroll
                for (int d = 0; d < 5; d++) red[js*5 + d] = fold2(acc[js][d]);
        }
        __syncthreads();

        // ---- phase B ----
        {
            const int q2b = jj >> 1, jsel = jj & 1;
            const float* r0 = sm + RED_OFF + ((0*2 + q2b) * 64 + b2) * 10 + jsel * 5;
            const float* r1 = sm + RED_OFF + ((1*2 + q2b) * 64 + b2) * 10 + jsel * 5;
            float pf = r0[0] + r1[0];
            float pi = r0[1] + r1[1];
            float po = r0[2] + r1[2];
            float pt = r0[3] + r1[3];
            float pd = r0[4] + r1[4];

            float dec  = 1.0f / logf(2.718281828459045f + tv);
            float cs1  = tanhf(pd + bdj);
            float cadj = (c_old - cs1) + cs1 * dec;
            float f  = sigf(pf + bfb + u0);
            float ii = sigf(pi + bib + u1);
            float o  = sigf(po + bob + u2);
            float ct = tanhf(pt + bcb + u3);
            float cn = f * cadj + ii * ct;
            float hn = o * tanhf(cn);

            const int nb = (s + 1) & 1;
            const int ij = b2 * HH + j;
            g_h[nb][ij] = hn;
            g_c[nb][ij] = cn;
            out[((size_t)b2 * SS + s) * HH + j] = hn;
            if (s == SS - 1) {
                out[BSH + ij] = hn;
                out[BSH + BB * HH + ij] = cn;
            }
        }

        // ---- grid barrier ----
        if (s < SS - 1) {
            __threadfence();
            __syncthreads();
            if (tid == 0) {
                atomicAdd(&g_ctr, 1u);
                unsigned tgt = (unsigned)(s + 1) * NBLK;
                volatile unsigned* pc = &g_ctr;
                while (*pc < tgt) { }
            }
            __syncthreads();
        }
    }
}

extern "C" void kernel_launch(void* const* d_in, const int* in_sizes, int n_in,
                              void* d_out, int out_size) {
    const float* inputs = (const float*)d_in[0];
    const float* tstamp = (const float*)d_in[1];
    const float* Wall   = (const float*)d_in[2];
    const float* ball   = (const float*)d_in[3];
    const float* Uall   = (const float*)d_in[4];
    const float* uball  = (const float*)d_in[5];
    const float* Wd     = (const float*)d_in[6];
    const float* bd     = (const float*)d_in[7];
    float* out = (float*)d_out;

    cudaFuncSetAttribute(lstm_scan, cudaFuncAttributeMaxDynamicSharedMemorySize, SCAN_SMEM);

    init_state<<<128, 256>>>();
    dim3 g1(GG / 128, (BB * SS) / 128);
    gemm_uproj<<<g1, 256>>>(inputs, Uall, uball);
    lstm_scan<<<NBLK, 256, SCAN_SMEM>>>(tstamp, Wall, ball, Wd, bd, out);
}

// round 5
// speedup vs baseline: 2.1207x; 2.1207x over previous
#include <cuda_runtime.h>
#include <cstdint>
#include <math.h>

typedef unsigned long long ull;

#define BB 64
#define SS 512
#define EE 256
#define HH 512
#define GG 2048
#define BSH (BB*SS*HH)
#define NBLK 128

// scan smem layout (float offsets)
#define SW_OFF 0            // [40][514] weights
#define X_OFF  20576        // 2 slots x (xh[32][130] + xc[32][130])
#define SLOT   8320
#define XC_OFF 4160
#define RED_OFF 20576       // overlaps X slots (used after all tiles consumed)
#define SMEM_FLOATS 37216
#define SCAN_SMEM (SMEM_FLOATS*4)

__device__ float g_uproj[BB*SS*GG];
__device__ float g_h[2][BB*HH];
__device__ float g_c[2][BB*HH];
__device__ unsigned int g_ctr;

// ---------------- helpers ----------------
__device__ __forceinline__ void ffma2(ull& d, ull a, ull b) {
    asm("fma.rn.f32x2 %0, %1, %2, %0;" : "+l"(d) : "l"(a), "l"(b));
}
__device__ __forceinline__ ull dup2(float a) {
    ull r; asm("mov.b64 %0, {%1,%1};" : "=l"(r) : "f"(a)); return r;
}
__device__ __forceinline__ float fold2(ull v) {
    float lo, hi;
    asm("mov.b64 {%0,%1}, %2;" : "=f"(lo), "=f"(hi) : "l"(v));
    return lo + hi;
}
__device__ __forceinline__ float sigf(float x) { return 1.0f / (1.0f + expf(-x)); }

// ---------------- init ----------------
__global__ void init_state() {
    int i = blockIdx.x * 256 + threadIdx.x;  // 32768
    g_h[0][i] = 0.f;
    g_c[0][i] = 0.f;
    if (i == 0) g_ctr = 0u;
}

// ---------------- u_proj GEMM (FFMA2, passed R4) ----------------
__global__ void __launch_bounds__(256) gemm_uproj(
    const float* __restrict__ A, const float* __restrict__ W, const float* __restrict__ bias)
{
    __shared__ float As[8][132];
    __shared__ float Bs[8][132];
    const int tid = threadIdx.x;
    const int bm = blockIdx.y * 128, bn = blockIdx.x * 128;
    const int tx = tid & 15, ty = tid >> 4;
    const int lrow = tid >> 1, lk = (tid & 1) * 4;
    const float* Aptr = A + (size_t)(bm + lrow) * EE + lk;
    const float* Wptr = W + (size_t)(bn + lrow) * EE + lk;

    ull acc2[8][4];
#pragma unroll
    for (int r = 0; r < 8; r++)
#pragma unroll
        for (int c = 0; c < 4; c++) acc2[r][c] = 0ull;

    float4 av = *(const float4*)(Aptr);
    float4 bv = *(const float4*)(Wptr);

    for (int k0 = 0; k0 < EE; k0 += 8) {
        __syncthreads();
        As[lk+0][lrow]=av.x; As[lk+1][lrow]=av.y; As[lk+2][lrow]=av.z; As[lk+3][lrow]=av.w;
        Bs[lk+0][lrow]=bv.x; Bs[lk+1][lrow]=bv.y; Bs[lk+2][lrow]=bv.z; Bs[lk+3][lrow]=bv.w;
        __syncthreads();
        if (k0 + 8 < EE) { av = *(const float4*)(Aptr+k0+8); bv = *(const float4*)(Wptr+k0+8); }
#pragma unroll
        for (int kk = 0; kk < 8; kk++) {
            float4 a0 = *(const float4*)&As[kk][ty*8];
            float4 a1 = *(const float4*)&As[kk][ty*8+4];
            ulonglong2 b0 = *(const ulonglong2*)&Bs[kk][tx*8];
            ulonglong2 b1 = *(const ulonglong2*)&Bs[kk][tx*8+4];
            float ar[8] = {a0.x,a0.y,a0.z,a0.w,a1.x,a1.y,a1.z,a1.w};
            ull br2[4] = {b0.x, b0.y, b1.x, b1.y};
#pragma unroll
            for (int r = 0; r < 8; r++) {
                ull ad = dup2(ar[r]);
#pragma unroll
                for (int c = 0; c < 4; c++) ffma2(acc2[r][c], ad, br2[c]);
            }
        }
    }

    float bsr[8];
#pragma unroll
    for (int c = 0; c < 8; c++) bsr[c] = bias[bn + tx*8 + c];
#pragma unroll
    for (int r = 0; r < 8; r++) {
        float accv[8];
#pragma unroll
        for (int c = 0; c < 4; c++) {
            float lo, hi;
            asm("mov.b64 {%0,%1}, %2;" : "=f"(lo), "=f"(hi) : "l"(acc2[r][c]));
            accv[2*c] = lo; accv[2*c+1] = hi;
        }
        float* cp = g_uproj + (size_t)(bm + ty*8 + r) * GG + bn + tx*8;
        float4 o0 = {accv[0]+bsr[0], accv[1]+bsr[1], accv[2]+bsr[2], accv[3]+bsr[3]};
        float4 o1 = {accv[4]+bsr[4], accv[5]+bsr[5], accv[6]+bsr[6], accv[7]+bsr[7]};
        *(float4*)(cp) = o0; *(float4*)(cp + 4) = o1;
    }
}

// ---------------- persistent scan: register-blocked FFMA2 GEMM ----------------
// Block bid: jg = bid>>1 (8 j's), bg = bid&1 (32 b's).
// Rows r=0..39: t = r>>3 in {f,i,o,cT,wd}, j = jbase + (r&7). Rows 0-31 use h, 32-39 use c.
// Warp w: rg = w&3 (rows rg*10..+9), khalf = w>>2. Lane: ksub = lane>>3, cg = lane&7.
// Thread: k-slice ks = khalf*4+ksub (16 k per 128-tile), rows rg*10..+9, cols b = cg+8i.
__global__ void __launch_bounds__(256, 1) lstm_scan(
    const float* __restrict__ ts,
    const float* __restrict__ Wall,
    const float* __restrict__ ball,
    const float* __restrict__ Wd,
    const float* __restrict__ bd,
    float* __restrict__ out)
{
    extern __shared__ float sm[];
    const int tid = threadIdx.x;
    const int bid = blockIdx.x;
    const int jbase = (bid >> 1) * 8;
    const int bbase = (bid & 1) * 32;

    // ---- weights -> smem (stride 514), once ----
    for (int idx = tid; idx < 40*512; idx += 256) {
        int row = idx >> 9, k = idx & 511;
        int t = row >> 3, jr = jbase + (row & 7);
        float v = (t < 4) ? __ldg(Wall + (size_t)(t*512 + jr)*512 + k)
                          : __ldg(Wd + (size_t)jr*512 + k);
        sm[SW_OFF + row*514 + k] = v;
    }

    // compute identity
    const int w    = tid >> 5;
    const int lane = tid & 31;
    const int rg   = w & 3;
    const int khalf= w >> 2;
    const int ksub = lane >> 3;
    const int cg   = lane & 7;
    const int ks16 = (khalf*4 + ksub) * 16;

    // staging identity: b-row sb (0..31), sub ss (0..7); chunks ss,ss+8,ss+16,ss+24
    const int sb = tid >> 3;
    const int ss = tid & 7;

    // phase-B identity: bb = tid>>3, jj = tid&7
    const int pb = tid >> 3;
    const int pj = tid & 7;
    const int b2 = bbase + pb;
    const int j  = jbase + pj;
    const float bfb = __ldg(ball + j);
    const float bib = __ldg(ball + 512 + j);
    const float bob = __ldg(ball + 1024 + j);
    const float bcb = __ldg(ball + 1536 + j);
    const float bdj = __ldg(bd + j);

    __syncthreads();

    for (int s = 0; s < SS; s++) {
        const float* hsrc = g_h[s & 1];
        const float* csrc = g_c[s & 1];

        // phase-B operand prefetch
        const float* up = g_uproj + ((size_t)b2 * SS + s) * GG;
        float u0 = __ldg(up + j);
        float u1 = __ldg(up + 512 + j);
        float u2 = __ldg(up + 1024 + j);
        float u3 = __ldg(up + 1536 + j);
        float tv = __ldg(ts + b2 * SS + s);
        float c_old = __ldcg(csrc + b2 * HH + j);

        float4 rh[4], rc[4];
        const float* hrow = hsrc + (size_t)(bbase + sb) * HH;
        const float* crow = csrc + (size_t)(bbase + sb) * HH;

        // preload tile 0, store, preload tile 1
#pragma unroll
        for (int u = 0; u < 4; u++) {
            rh[u] = __ldcg((const float4*)(hrow + (ss + 8*u) * 4));
            rc[u] = __ldcg((const float4*)(crow + (ss + 8*u) * 4));
        }
        {
            float* dh = sm + X_OFF + sb*130;
            float* dc = dh + XC_OFF;
#pragma unroll
            for (int u = 0; u < 4; u++) {
                int o = (ss + 8*u) * 4;
                *(float2*)(dh + o)     = make_float2(rh[u].x, rh[u].y);
                *(float2*)(dh + o + 2) = make_float2(rh[u].z, rh[u].w);
                *(float2*)(dc + o)     = make_float2(rc[u].x, rc[u].y);
                *(float2*)(dc + o + 2) = make_float2(rc[u].z, rc[u].w);
            }
        }
#pragma unroll
        for (int u = 0; u < 4; u++) {
            rh[u] = __ldcg((const float4*)(hrow + 128 + (ss + 8*u) * 4));
            rc[u] = __ldcg((const float4*)(crow + 128 + (ss + 8*u) * 4));
        }
        __syncthreads();

        ull acc[10][4];
#pragma unroll
        for (int rl = 0; rl < 10; rl++)
#pragma unroll
            for (int i = 0; i < 4; i++) acc[rl][i] = 0ull;

#pragma unroll 1
        for (int t = 0; t < 4; t++) {
            const float* xb = sm + X_OFF + (t & 1) * SLOT + cg * 130 + ks16;
            const float* wb = sm + SW_OFF + rg * 10 * 514 + t * 128 + ks16;
            if (rg < 3) {
#pragma unroll
                for (int kk = 0; kk < 8; kk++) {
                    ull x0 = *(const ull*)(xb + 2*kk);
                    ull x1 = *(const ull*)(xb + 1040 + 2*kk);
                    ull x2 = *(const ull*)(xb + 2080 + 2*kk);
                    ull x3 = *(const ull*)(xb + 3120 + 2*kk);
#pragma unroll
                    for (int rl = 0; rl < 10; rl++) {
                        ull wv = *(const ull*)(wb + rl*514 + 2*kk);
                        ffma2(acc[rl][0], wv, x0);
                        ffma2(acc[rl][1], wv, x1);
                        ffma2(acc[rl][2], wv, x2);
                        ffma2(acc[rl][3], wv, x3);
                    }
                }
            } else {
                const float* xcb = xb + XC_OFF;
#pragma unroll
                for (int kk = 0; kk < 8; kk++) {
                    ull h0 = *(const ull*)(xb + 2*kk);
                    ull h1 = *(const ull*)(xb + 1040 + 2*kk);
                    ull h2 = *(const ull*)(xb + 2080 + 2*kk);
                    ull h3 = *(const ull*)(xb + 3120 + 2*kk);
                    ull c0 = *(const ull*)(xcb + 2*kk);
                    ull c1 = *(const ull*)(xcb + 1040 + 2*kk);
                    ull c2 = *(const ull*)(xcb + 2080 + 2*kk);
                    ull c3 = *(const ull*)(xcb + 3120 + 2*kk);
#pragma unroll
                    for (int rl = 0; rl < 2; rl++) {
                        ull wv = *(const ull*)(wb + rl*514 + 2*kk);
                        ffma2(acc[rl][0], wv, h0);
                        ffma2(acc[rl][1], wv, h1);
                        ffma2(acc[rl][2], wv, h2);
                        ffma2(acc[rl][3], wv, h3);
                    }
#pragma unroll
                    for (int rl = 2; rl < 10; rl++) {
                        ull wv = *(const ull*)(wb + rl*514 + 2*kk);
                        ffma2(acc[rl][0], wv, c0);
                        ffma2(acc[rl][1], wv, c1);
                        ffma2(acc[rl][2], wv, c2);
                        ffma2(acc[rl][3], wv, c3);
                    }
                }
            }
            if (t < 3) {
                // store tile t+1 into slot (t+1)&1 (its previous readers done at last sync)
                float* dh = sm + X_OFF + ((t + 1) & 1) * SLOT + sb*130;
                float* dc = dh + XC_OFF;
#pragma unroll
                for (int u = 0; u < 4; u++) {
                    int o = (ss + 8*u) * 4;
                    *(float2*)(dh + o)     = make_float2(rh[u].x, rh[u].y);
                    *(float2*)(dh + o + 2) = make_float2(rh[u].z, rh[u].w);
                    *(float2*)(dc + o)     = make_float2(rc[u].x, rc[u].y);
                    *(float2*)(dc + o + 2) = make_float2(rc[u].z, rc[u].w);
                }
                if (t < 2) {
                    int tb = (t + 2) * 128;
#pragma unroll
                    for (int u = 0; u < 4; u++) {
                        rh[u] = __ldcg((const float4*)(hrow + tb + (ss + 8*u) * 4));
                        rc[u] = __ldcg((const float4*)(crow + tb + (ss + 8*u) * 4));
                    }
                }
            }
            __syncthreads();
        }

        // ---- block-local reduction: partials -> smem (overlaps x slots) ----
        {
            const int ksl = khalf*4 + ksub;
#pragma unroll
            for (int rl = 0; rl < 10; rl++) {
                int row = rg*10 + rl;
#pragma unroll
                for (int i = 0; i < 4; i++) {
                    int bbx = cg + 8*i;
                    sm[RED_OFF + ((row*32 + bbx) << 3) + ksl] = fold2(acc[rl][i]);
                }
            }
        }
        __syncthreads();

        // ---- phase B ----
        {
            float p[5];
#pragma unroll
            for (int t = 0; t < 5; t++) {
                const float4* r0 = (const float4*)(sm + RED_OFF + (((t*8 + pj)*32 + pb) << 3));
                float4 a = r0[0], bq = r0[1];
                p[t] = ((a.x + a.y) + (a.z + a.w)) + ((bq.x + bq.y) + (bq.z + bq.w));
            }
            float dec  = 1.0f / logf(2.718281828459045f + tv);
            float cs1  = tanhf(p[4] + bdj);
            float cadj = (c_old - cs1) + cs1 * dec;
            float f  = sigf(p[0] + bfb + u0);
            float ii = sigf(p[1] + bib + u1);
            float o  = sigf(p[2] + bob + u2);
            float ct = tanhf(p[3] + bcb + u3);
            float cn = f * cadj + ii * ct;
            float hn = o * tanhf(cn);

            const int nb = (s + 1) & 1;
            const int ij = b2 * HH + j;
            g_h[nb][ij] = hn;
            g_c[nb][ij] = cn;
            out[((size_t)b2 * SS + s) * HH + j] = hn;
            if (s == SS - 1) {
                out[BSH + ij] = hn;
                out[BSH + BB * HH + ij] = cn;
            }
        }

        // ---- grid barrier ----
        if (s < SS - 1) {
            __threadfence();
            __syncthreads();
            if (tid == 0) {
                atomicAdd(&g_ctr, 1u);
                unsigned tgt = (unsigned)(s + 1) * NBLK;
                volatile unsigned* pc = &g_ctr;
                while (*pc < tgt) { }
            }
            __syncthreads();
        }
    }
}

extern "C" void kernel_launch(void* const* d_in, const int* in_sizes, int n_in,
                              void* d_out, int out_size) {
    const float* inputs = (const float*)d_in[0];
    const float* tstamp = (const float*)d_in[1];
    const float* Wall   = (const float*)d_in[2];
    const float* ball   = (const float*)d_in[3];
    const float* Uall   = (const float*)d_in[4];
    const float* uball  = (const float*)d_in[5];
    const float* Wd     = (const float*)d_in[6];
    const float* bd     = (const float*)d_in[7];
    float* out = (float*)d_out;

    cudaFuncSetAttribute(lstm_scan, cudaFuncAttributeMaxDynamicSharedMemorySize, SCAN_SMEM);

    init_state<<<128, 256>>>();
    dim3 g1(GG / 128, (BB * SS) / 128);
    gemm_uproj<<<g1, 256>>>(inputs, Uall, uball);
    lstm_scan<<<NBLK, 256, SCAN_SMEM>>>(tstamp, Wall, ball, Wd, bd, out);
}